// round 10
// baseline (speedup 1.0000x reference)
#include <cuda_runtime.h>
#include <mma.h>

using namespace nvcuda;

#define N_NODES 100000
#define IN_DIM 500
#define HID 32
#define HEADS 4
#define F1 128            // HEADS*HID
#define OUT_DIM 3
#define NEG 0.2f

// ---------------- scratch (device globals; no allocation allowed) ----------
__device__ float g_z1[N_NODES * F1];
__device__ float g_el1[N_NODES * HEADS];
__device__ float g_er1[N_NODES * HEADS];
__device__ float g_h[N_NODES * F1];
__device__ float g_z2[N_NODES * OUT_DIM];
__device__ float g_el2[N_NODES];
__device__ float g_er2[N_NODES];
__device__ int   g_row[N_NODES + 1];

// ---------------- CSR row offsets from sorted dst --------------------------
__global__ void build_offsets(const int* __restrict__ dst, int E) {
    int i = blockIdx.x * blockDim.x + threadIdx.x;
    if (i >= E) return;
    int d = dst[i];
    if (i == 0) {
        for (int n = 0; n <= d; n++) g_row[n] = 0;
    } else {
        int pd = dst[i - 1];
        for (int n = pd + 1; n <= d; n++) g_row[n] = i;
    }
    if (i == E - 1) {
        for (int n = d + 1; n <= N_NODES; n++) g_row[n] = E;
    }
}

// ---------------- GEMM1 (3xTF32 tensor core): z1 = X @ W1 ------------------
// 64x128 block tile, BK=16, 256 threads (8 warps, 2x4), warp = 32x32.
// Split-precision: x = hi + lo (hi = tf32-truncated); acc += hi*hi + hi*lo + lo*hi.
// Epilogue (via smem staging) stores z1 + fused el1/er1.
#define LDA 20     // 16 + 4 pad
#define LDB 132    // 128 + 4 pad
#define LDC 132

__global__ void __launch_bounds__(256) gemm1_kernel(const float* __restrict__ X,
                                                    const float* __restrict__ W,
                                                    const float* __restrict__ al,
                                                    const float* __restrict__ ar) {
    __shared__ __align__(16) char smem_raw[64 * LDC * 4];  // 33792 B (union)
    float* A_hi = reinterpret_cast<float*>(smem_raw);      // 64*LDA
    float* A_lo = A_hi + 64 * LDA;
    float* B_hi = A_lo + 64 * LDA;                         // 16*LDB
    float* B_lo = B_hi + 16 * LDB;
    float* Cst  = reinterpret_cast<float*>(smem_raw);      // 64*LDC (reuse)

    int tid = threadIdx.x;
    int wid = tid >> 5;
    int m0 = blockIdx.x * 64;
    int wm = wid >> 2;        // 0..1 -> warp row (32 rows)
    int wn = wid & 3;         // 0..3 -> warp col (32 cols)

    wmma::fragment<wmma::accumulator, 16, 16, 8, float> acc[2][2];
#pragma unroll
    for (int i = 0; i < 2; i++)
#pragma unroll
        for (int j = 0; j < 2; j++) wmma::fill_fragment(acc[i][j], 0.f);

    // per-thread load coords
    int a_row = tid >> 2, a_kc4 = (tid & 3) * 4;           // A: 64 rows x 4 float4
    for (int k0 = 0; k0 < IN_DIM; k0 += 16) {
        // ---- stage A (64x16 hi/lo) ----
        {
            int gm = m0 + a_row, gk = k0 + a_kc4;
            float4 v = make_float4(0.f, 0.f, 0.f, 0.f);
            if (gm < N_NODES && gk < IN_DIM)
                v = *reinterpret_cast<const float4*>(&X[(long)gm * IN_DIM + gk]);
            float* ah = &A_hi[a_row * LDA + a_kc4];
            float* alo = &A_lo[a_row * LDA + a_kc4];
            float h0 = __uint_as_float(__float_as_uint(v.x) & 0xFFFFE000u);
            float h1 = __uint_as_float(__float_as_uint(v.y) & 0xFFFFE000u);
            float h2 = __uint_as_float(__float_as_uint(v.z) & 0xFFFFE000u);
            float h3 = __uint_as_float(__float_as_uint(v.w) & 0xFFFFE000u);
            ah[0] = h0; ah[1] = h1; ah[2] = h2; ah[3] = h3;
            alo[0] = v.x - h0; alo[1] = v.y - h1; alo[2] = v.z - h2; alo[3] = v.w - h3;
        }
        // ---- stage B (16x128 hi/lo) ----
#pragma unroll
        for (int p = 0; p < 2; p++) {
            int idx = tid + p * 256;
            int krow = idx >> 5, n4 = (idx & 31) * 4;
            int gk = k0 + krow;
            float4 v = make_float4(0.f, 0.f, 0.f, 0.f);
            if (gk < IN_DIM)
                v = *reinterpret_cast<const float4*>(&W[gk * F1 + n4]);
            float* bh = &B_hi[krow * LDB + n4];
            float* blo = &B_lo[krow * LDB + n4];
            float h0 = __uint_as_float(__float_as_uint(v.x) & 0xFFFFE000u);
            float h1 = __uint_as_float(__float_as_uint(v.y) & 0xFFFFE000u);
            float h2 = __uint_as_float(__float_as_uint(v.z) & 0xFFFFE000u);
            float h3 = __uint_as_float(__float_as_uint(v.w) & 0xFFFFE000u);
            bh[0] = h0; bh[1] = h1; bh[2] = h2; bh[3] = h3;
            blo[0] = v.x - h0; blo[1] = v.y - h1; blo[2] = v.z - h2; blo[3] = v.w - h3;
        }
        __syncthreads();
        // ---- compute: 2 k-frags per stage ----
#pragma unroll
        for (int kf = 0; kf < 2; kf++) {
            wmma::fragment<wmma::matrix_a, 16, 16, 8, wmma::precision::tf32, wmma::row_major> ah[2], alo[2];
            wmma::fragment<wmma::matrix_b, 16, 16, 8, wmma::precision::tf32, wmma::row_major> bh[2], blo[2];
#pragma unroll
            for (int i = 0; i < 2; i++) {
                const float* base = &A_hi[(wm * 32 + i * 16) * LDA + kf * 8];
                wmma::load_matrix_sync(ah[i], base, LDA);
                wmma::load_matrix_sync(alo[i], &A_lo[(wm * 32 + i * 16) * LDA + kf * 8], LDA);
            }
#pragma unroll
            for (int j = 0; j < 2; j++) {
                wmma::load_matrix_sync(bh[j], &B_hi[kf * 8 * LDB + wn * 32 + j * 16], LDB);
                wmma::load_matrix_sync(blo[j], &B_lo[kf * 8 * LDB + wn * 32 + j * 16], LDB);
            }
#pragma unroll
            for (int i = 0; i < 2; i++)
#pragma unroll
                for (int j = 0; j < 2; j++) {
                    wmma::mma_sync(acc[i][j], ah[i], bh[j], acc[i][j]);
                    wmma::mma_sync(acc[i][j], ah[i], blo[j], acc[i][j]);
                    wmma::mma_sync(acc[i][j], alo[i], bh[j], acc[i][j]);
                }
        }
        __syncthreads();
    }

    // ---- epilogue: stage C in smem, then z1 + fused el1/er1 ----
#pragma unroll
    for (int i = 0; i < 2; i++)
#pragma unroll
        for (int j = 0; j < 2; j++)
            wmma::store_matrix_sync(&Cst[(wm * 32 + i * 16) * LDC + wn * 32 + j * 16],
                                    acc[i][j], LDC, wmma::mem_row_major);
    __syncthreads();

    // el/er: one thread per (row, head)
    {
        int row = tid >> 2;
        int head = tid & 3;
        int gm = m0 + row;
        if (gm < N_NODES) {
            const float* zr = &Cst[row * LDC + head * HID];
            float pl = 0.f, pr = 0.f;
#pragma unroll
            for (int c = 0; c < HID; c++) {
                float z = zr[c];
                pl += z * al[head * HID + c];
                pr += z * ar[head * HID + c];
            }
            g_el1[gm * HEADS + head] = pl;
            g_er1[gm * HEADS + head] = pr;
        }
    }
    // z1 copy-out: 64 rows x 32 float4
#pragma unroll
    for (int i = 0; i < 8; i++) {
        int idx = tid + i * 256;
        int row = idx >> 5, c4 = (idx & 31) * 4;
        int gm = m0 + row;
        if (gm < N_NODES) {
            float4 v = *reinterpret_cast<const float4*>(&Cst[row * LDC + c4]);
            *reinterpret_cast<float4*>(&g_z1[(long)gm * F1 + c4]) = v;
        }
    }
}

// ---------------- layer1: online edge-softmax + aggregate + bias + ELU -----
// one warp per dst node; single pass, 4-edge batches for MLP.
__global__ void agg1_kernel(const int* __restrict__ src, const float* __restrict__ b1) {
    int warp = (blockIdx.x * blockDim.x + threadIdx.x) >> 5;
    int lane = threadIdx.x & 31;
    if (warp >= N_NODES) return;
    int n = warp;
    int s0 = g_row[n], s1 = g_row[n + 1];
    int h = lane >> 3;
    float ern = g_er1[n * HEADS + h];
    int coff = lane * 4;

    float m = -1e30f;
    float denom = 0.f;
    float a0 = 0.f, a1 = 0.f, a2 = 0.f, a3 = 0.f;

    int j = s0;
    for (; j + 4 <= s1; j += 4) {
        int sA = src[j], sB = src[j + 1], sC = src[j + 2], sD = src[j + 3];
        float eA = g_el1[sA * HEADS + h] + ern;
        float eB = g_el1[sB * HEADS + h] + ern;
        float eC = g_el1[sC * HEADS + h] + ern;
        float eD = g_el1[sD * HEADS + h] + ern;
        float4 zA = *reinterpret_cast<const float4*>(&g_z1[(long)sA * F1 + coff]);
        float4 zB = *reinterpret_cast<const float4*>(&g_z1[(long)sB * F1 + coff]);
        float4 zC = *reinterpret_cast<const float4*>(&g_z1[(long)sC * F1 + coff]);
        float4 zD = *reinterpret_cast<const float4*>(&g_z1[(long)sD * F1 + coff]);
        eA = eA > 0.f ? eA : NEG * eA;
        eB = eB > 0.f ? eB : NEG * eB;
        eC = eC > 0.f ? eC : NEG * eC;
        eD = eD > 0.f ? eD : NEG * eD;
        float mn = fmaxf(fmaxf(fmaxf(m, eA), fmaxf(eB, eC)), eD);
        float c  = __expf(m - mn);
        float pA = __expf(eA - mn);
        float pB = __expf(eB - mn);
        float pC = __expf(eC - mn);
        float pD = __expf(eD - mn);
        m = mn;
        denom = denom * c + ((pA + pB) + (pC + pD));
        a0 = a0 * c + zA.x * pA + zB.x * pB + zC.x * pC + zD.x * pD;
        a1 = a1 * c + zA.y * pA + zB.y * pB + zC.y * pC + zD.y * pD;
        a2 = a2 * c + zA.z * pA + zB.z * pB + zC.z * pC + zD.z * pD;
        a3 = a3 * c + zA.w * pA + zB.w * pB + zC.w * pC + zD.w * pD;
    }
    for (; j < s1; j++) {
        int s = src[j];
        float e = g_el1[s * HEADS + h] + ern;
        e = e > 0.f ? e : NEG * e;
        float mn = fmaxf(m, e);
        float c = __expf(m - mn);
        float p = __expf(e - mn);
        m = mn;
        denom = denom * c + p;
        float4 z = *reinterpret_cast<const float4*>(&g_z1[(long)s * F1 + coff]);
        a0 = a0 * c + z.x * p;
        a1 = a1 * c + z.y * p;
        a2 = a2 * c + z.z * p;
        a3 = a3 * c + z.w * p;
    }

    float inv = 1.f / fmaxf(denom, 1e-9f);
    float4 bb = *reinterpret_cast<const float4*>(&b1[coff]);
    float o0 = a0 * inv + bb.x;
    float o1 = a1 * inv + bb.y;
    float o2 = a2 * inv + bb.z;
    float o3 = a3 * inv + bb.w;
    o0 = o0 > 0.f ? o0 : expm1f(o0);
    o1 = o1 > 0.f ? o1 : expm1f(o1);
    o2 = o2 > 0.f ? o2 : expm1f(o2);
    o3 = o3 > 0.f ? o3 : expm1f(o3);
    *reinterpret_cast<float4*>(&g_h[(long)n * F1 + coff]) = make_float4(o0, o1, o2, o3);
}

// ---------------- GEMM2 + el2/er2: z2 = h @ W2[128,3] ----------------------
__global__ void gemm2_kernel(const float* __restrict__ W2, const float* __restrict__ al2,
                             const float* __restrict__ ar2) {
    __shared__ float sW[F1 * OUT_DIM];
    int tid = threadIdx.x;
    for (int i = tid; i < F1 * OUT_DIM; i += blockDim.x) sW[i] = W2[i];
    __syncthreads();
    int warp = (blockIdx.x * blockDim.x + tid) >> 5;
    int lane = tid & 31;
    if (warp >= N_NODES) return;
    float4 hv = *reinterpret_cast<const float4*>(&g_h[(long)warp * F1 + lane * 4]);
    float v[4] = {hv.x, hv.y, hv.z, hv.w};
    float p0 = 0.f, p1 = 0.f, p2 = 0.f;
#pragma unroll
    for (int t = 0; t < 4; t++) {
        int k = lane * 4 + t;
        p0 += v[t] * sW[k * 3 + 0];
        p1 += v[t] * sW[k * 3 + 1];
        p2 += v[t] * sW[k * 3 + 2];
    }
#pragma unroll
    for (int o = 16; o; o >>= 1) {
        p0 += __shfl_xor_sync(0xffffffffu, p0, o);
        p1 += __shfl_xor_sync(0xffffffffu, p1, o);
        p2 += __shfl_xor_sync(0xffffffffu, p2, o);
    }
    if (lane == 0) {
        g_z2[warp * 3 + 0] = p0;
        g_z2[warp * 3 + 1] = p1;
        g_z2[warp * 3 + 2] = p2;
        g_el2[warp] = p0 * al2[0] + p1 * al2[1] + p2 * al2[2];
        g_er2[warp] = p0 * ar2[0] + p1 * ar2[1] + p2 * ar2[2];
    }
}

// ---------------- layer2 edge-softmax + aggregate + bias -> out ------------
__global__ void agg2_kernel(const int* __restrict__ src, const float* __restrict__ b2,
                            float* __restrict__ out) {
    int warp = (blockIdx.x * blockDim.x + threadIdx.x) >> 5;
    int lane = threadIdx.x & 31;
    if (warp >= N_NODES) return;
    int n = warp;
    int s0 = g_row[n], s1 = g_row[n + 1];
    float ern = g_er2[n];
    float m = -1e30f;
    for (int j = s0 + lane; j < s1; j += 32) {
        float e = g_el2[src[j]] + ern;
        e = e > 0.f ? e : NEG * e;
        m = fmaxf(m, e);
    }
#pragma unroll
    for (int o = 16; o; o >>= 1) m = fmaxf(m, __shfl_xor_sync(0xffffffffu, m, o));
    float sd = 0.f, a0 = 0.f, a1 = 0.f, a2 = 0.f;
    for (int j = s0 + lane; j < s1; j += 32) {
        int s = src[j];
        float e = g_el2[s] + ern;
        e = e > 0.f ? e : NEG * e;
        float p = __expf(e - m);
        sd += p;
        a0 += p * g_z2[s * 3 + 0];
        a1 += p * g_z2[s * 3 + 1];
        a2 += p * g_z2[s * 3 + 2];
    }
#pragma unroll
    for (int o = 16; o; o >>= 1) {
        sd += __shfl_xor_sync(0xffffffffu, sd, o);
        a0 += __shfl_xor_sync(0xffffffffu, a0, o);
        a1 += __shfl_xor_sync(0xffffffffu, a1, o);
        a2 += __shfl_xor_sync(0xffffffffu, a2, o);
    }
    if (lane < 3) {
        float inv = 1.f / fmaxf(sd, 1e-9f);
        float acc = (lane == 0) ? a0 : (lane == 1) ? a1 : a2;
        out[n * 3 + lane] = acc * inv + b2[lane];
    }
}

// ---------------- launch ----------------------------------------------------
extern "C" void kernel_launch(void* const* d_in, const int* in_sizes, int n_in,
                              void* d_out, int out_size) {
    const float* features = (const float*)d_in[0];
    const int*   src      = (const int*)d_in[1];
    const int*   dst      = (const int*)d_in[2];
    const float* W1       = (const float*)d_in[3];
    const float* al1      = (const float*)d_in[4];
    const float* ar1      = (const float*)d_in[5];
    const float* b1       = (const float*)d_in[6];
    const float* W2       = (const float*)d_in[7];
    const float* al2      = (const float*)d_in[8];
    const float* ar2      = (const float*)d_in[9];
    const float* b2       = (const float*)d_in[10];
    float* out = (float*)d_out;
    int E = in_sizes[1];

    build_offsets<<<(E + 255) / 256, 256>>>(dst, E);
    gemm1_kernel<<<(N_NODES + 63) / 64, 256>>>(features, W1, al1, ar1);

    int warps_blocks = (N_NODES * 32 + 255) / 256;   // 8 warps/block
    agg1_kernel<<<warps_blocks, 256>>>(src, b1);
    gemm2_kernel<<<warps_blocks, 256>>>(W2, al2, ar2);
    agg2_kernel<<<warps_blocks, 256>>>(src, b2, out);
}